// round 2
// baseline (speedup 1.0000x reference)
#include <cuda_runtime.h>
#include <cuda_bf16.h>
#include <math.h>

// Problem constants
#define BB 256
#define VV 16
#define TT 64
#define PP 24
#define FF 8
#define HH 256
#define G4 1024   // 4*H
#define OUTD 4

// ---------------- device scratch (static, allocation-free) ----------------
__device__ float g_enc[BB * VV * TT * HH];     // 256 MB encoder outputs
__device__ float g_hA[BB * VV * HH];
__device__ float g_hB[BB * VV * HH];
__device__ float g_c [BB * VV * HH];
__device__ float g_prev[BB * VV * FF];
__device__ float g_Whh[VV * HH * G4];          // k-major: [v][k][g]
__device__ float g_Wih[VV * FF * G4];          // [v][f][g]
__device__ float g_bg [VV * G4];               // b_ih + b_hh
__device__ float g_Watt[VV * 2 * HH * HH];     // [v][k][hcol], k in [0,512)

__device__ __forceinline__ float sigf(float x) {
    return 1.0f / (1.0f + __expf(-x));
}

// ---------------- prep: transpose weights to k-major ----------------
__global__ void prep_kernel(const float* __restrict__ Wih,
                            const float* __restrict__ Whh,
                            const float* __restrict__ bih,
                            const float* __restrict__ bhh,
                            const float* __restrict__ Watt) {
    int idx0 = blockIdx.x * blockDim.x + threadIdx.x;
    int stride = gridDim.x * blockDim.x;
    // W_hh (V,4H,H) -> [v][k][g]
    for (int idx = idx0; idx < VV * G4 * HH; idx += stride) {
        int v = idx >> 18; int rem = idx & 262143; int g = rem >> 8; int k = rem & 255;
        g_Whh[(v * HH + k) * G4 + g] = Whh[idx];
    }
    // W_ih (V,4H,F) -> [v][f][g]
    for (int idx = idx0; idx < VV * G4 * FF; idx += stride) {
        int v = idx >> 13; int rem = idx & 8191; int g = rem >> 3; int f = rem & 7;
        g_Wih[(v * FF + f) * G4 + g] = Wih[idx];
    }
    for (int idx = idx0; idx < VV * G4; idx += stride)
        g_bg[idx] = bih[idx] + bhh[idx];
    // W_att (V,H,2H) -> [v][k][hcol]
    for (int idx = idx0; idx < VV * HH * 2 * HH; idx += stride) {
        int v = idx >> 17; int rem = idx & 131071; int h = rem >> 9; int k = rem & 511;
        g_Watt[(v * 512 + k) * HH + h] = Watt[idx];
    }
}

// ---------------- shared gate GEMM: gates[16][1024] = x[16][8]@Wih + h[16][256]@Whh ----------------
__device__ __forceinline__ void gates_gemm(const float* __restrict__ xs,   // [16][8]
                                           const float* __restrict__ hs,   // [16][256]
                                           const float* __restrict__ wih,  // v-base [f][1024]
                                           const float* __restrict__ whh,  // v-base [k][1024]
                                           float* __restrict__ gates_s,    // [16][1024]
                                           int tid) {
    const int c0 = tid * 4;
    float4 acc[16];
#pragma unroll
    for (int m = 0; m < 16; m++) acc[m] = make_float4(0.f, 0.f, 0.f, 0.f);
    // x part (K=8)
#pragma unroll
    for (int f = 0; f < 8; f++) {
        float4 w = *(const float4*)(wih + f * G4 + c0);
#pragma unroll
        for (int m = 0; m < 16; m++) {
            float xv = xs[m * 8 + f];
            acc[m].x = fmaf(xv, w.x, acc[m].x);
            acc[m].y = fmaf(xv, w.y, acc[m].y);
            acc[m].z = fmaf(xv, w.z, acc[m].z);
            acc[m].w = fmaf(xv, w.w, acc[m].w);
        }
    }
    // h part (K=256), k unrolled by 4
    const float* wb = whh + c0;
    for (int k = 0; k < 256; k += 4) {
        float4 w0 = *(const float4*)(wb + (k + 0) * G4);
        float4 w1 = *(const float4*)(wb + (k + 1) * G4);
        float4 w2 = *(const float4*)(wb + (k + 2) * G4);
        float4 w3 = *(const float4*)(wb + (k + 3) * G4);
#pragma unroll
        for (int m = 0; m < 16; m++) {
            float4 hv = *(const float4*)(hs + m * 256 + k);
            float4 a = acc[m];
            a.x = fmaf(hv.x, w0.x, a.x); a.y = fmaf(hv.x, w0.y, a.y);
            a.z = fmaf(hv.x, w0.z, a.z); a.w = fmaf(hv.x, w0.w, a.w);
            a.x = fmaf(hv.y, w1.x, a.x); a.y = fmaf(hv.y, w1.y, a.y);
            a.z = fmaf(hv.y, w1.z, a.z); a.w = fmaf(hv.y, w1.w, a.w);
            a.x = fmaf(hv.z, w2.x, a.x); a.y = fmaf(hv.z, w2.y, a.y);
            a.z = fmaf(hv.z, w2.z, a.z); a.w = fmaf(hv.z, w2.w, a.w);
            a.x = fmaf(hv.w, w3.x, a.x); a.y = fmaf(hv.w, w3.y, a.y);
            a.z = fmaf(hv.w, w3.z, a.z); a.w = fmaf(hv.w, w3.w, a.w);
            acc[m] = a;
        }
    }
#pragma unroll
    for (int m = 0; m < 16; m++)
        *(float4*)(gates_s + m * G4 + c0) = acc[m];
}

// ---------------- encoder: persistent per (v, batch chunk of 16) ----------------
// smem: gates[16384] | h[4096] | c[4096] | x[128]  -> 24704 floats
#define ENC_SMEM (24704 * 4)
__global__ __launch_bounds__(256, 2) void encoder_kernel(const float* __restrict__ seq) {
    extern __shared__ float sm[];
    float* gates_s = sm;
    float* h_s = sm + 16384;
    float* c_s = sm + 20480;
    float* x_s = sm + 24576;
    const int tid = threadIdx.x;
    const int v  = blockIdx.x >> 4;
    const int b0 = (blockIdx.x & 15) << 4;
    const float* wih = g_Wih + v * (FF * G4);
    const float* whh = g_Whh + v * (HH * G4);
    const float* bg  = g_bg + v * G4;

    for (int i = tid; i < 4096; i += 256) { h_s[i] = 0.f; c_s[i] = 0.f; }
    __syncthreads();

    for (int t = 0; t < TT; t++) {
        if (tid < 128) {
            int m = tid >> 3, f = tid & 7;
            x_s[tid] = seq[((b0 + m) * VV + v) * (TT * FF) + t * FF + f];
        }
        __syncthreads();
        gates_gemm(x_s, h_s, wih, whh, gates_s, tid);
        __syncthreads();
#pragma unroll
        for (int j = 0; j < 16; j++) {
            const int hc = tid;
            float gi = gates_s[j * G4 +        hc] + bg[hc];
            float gf = gates_s[j * G4 + 256 +  hc] + bg[256 + hc];
            float gg = gates_s[j * G4 + 512 +  hc] + bg[512 + hc];
            float go = gates_s[j * G4 + 768 +  hc] + bg[768 + hc];
            float c = sigf(gf) * c_s[j * 256 + hc] + sigf(gi) * tanhf(gg);
            float h = sigf(go) * tanhf(c);
            c_s[j * 256 + hc] = c;
            h_s[j * 256 + hc] = h;
            g_enc[(((b0 + j) * VV + v) * TT + t) * HH + hc] = h;
        }
        __syncthreads();
    }
    // final states + prev init
    for (int i = tid; i < 4096; i += 256) {
        int j = i >> 8, hc = i & 255;
        int gi = ((b0 + j) * VV + v) * HH + hc;
        g_hA[gi] = h_s[i];
        g_c[gi]  = c_s[i];
    }
    if (tid < 128) {
        int m = tid >> 3, f = tid & 7;
        g_prev[((b0 + m) * VV + v) * FF + f] =
            seq[((b0 + m) * VV + v) * (TT * FF) + (TT - 1) * FF + f];
    }
}

// ---------------- decoder step ----------------
// smem: A[16384] (hsrc[0:4096] | cat[4096:12288] | pad; reused as gates)
//       hatt[4096] (reused as h2) | c[4096] | prev[128] | ps[128] | scl[128] | mn[128]
#define DEC_SMEM (25088 * 4)
__global__ __launch_bounds__(256, 2) void decoder_kernel(
    const float* __restrict__ mask, const float* __restrict__ maxv,
    const float* __restrict__ minv, const float* __restrict__ batt,
    const float* __restrict__ wout, const float* __restrict__ bout,
    float* __restrict__ dout, int p) {
    extern __shared__ float sm[];
    float* hsrc   = sm;            // [16][256]
    float* cat    = sm + 4096;     // [16][512]
    float* gates_s= sm;            // reuse A after cat consumed
    float* hatt   = sm + 16384;    // [16][256]
    float* c_s    = sm + 20480;    // [16][256]
    float* prev_s = sm + 24576;    // [16][8]
    float* ps_s   = sm + 24704;
    float* scl_s  = sm + 24832;
    float* mn_s   = sm + 24960;
    const int tid = threadIdx.x;
    const int v  = blockIdx.x >> 4;
    const int ci = blockIdx.x & 15;
    const float* h_in  = (p & 1) ? g_hB : g_hA;
    float*       h_out = (p & 1) ? g_hA : g_hB;
    const float* bg = g_bg + v * G4;

    // load source-row hidden states: slot s -> row r = 2*ci + 32*(s>>1) + (s&1)
    for (int i = tid; i < 4096; i += 256) {
        int s = i >> 8, hc = i & 255;
        int r = 2 * ci + 32 * (s >> 1) + (s & 1);
        hsrc[i] = h_in[(r * VV + v) * HH + hc];
    }
    // own-row state (b2 = ci + 16*j)
    for (int i = tid; i < 4096; i += 256) {
        int j = i >> 8, hc = i & 255;
        int b2 = ci + 16 * j;
        c_s[i] = g_c[(b2 * VV + v) * HH + hc];
    }
    if (tid < 128) {
        int j = tid >> 3, f = tid & 7;
        int b2 = ci + 16 * j;
        prev_s[tid] = g_prev[(b2 * VV + v) * FF + f];
        float mx = maxv[b2 * FF + f], mn = minv[b2 * FF + f];
        scl_s[tid] = mx - mn;
        mn_s[tid]  = mn;
    }
    __syncthreads();

    // attention with online softmax: warp w handles source rows r0=2ci+32w, r1=r0+1
    {
        const int w = tid >> 5, lane = tid & 31;
        const int r0 = 2 * ci + 32 * w, r1 = r0 + 1;
        const float* e0 = g_enc + (size_t)(r0 * VV + v) * (TT * HH);
        const float* e1 = g_enc + (size_t)(r1 * VV + v) * (TT * HH);
        const float* mk0 = mask + (r0 * VV + v) * TT;
        const float* mk1 = mask + (r1 * VV + v) * TT;
        const float* h0 = hsrc + (2 * w) * 256;
        const float* h1 = h0 + 256;
        float cv0[8], cv1[8];
#pragma unroll
        for (int q = 0; q < 8; q++) { cv0[q] = 0.f; cv1[q] = 0.f; }
        float M0 = -1e30f, S0 = 0.f, M1 = -1e30f, S1 = 0.f;
        for (int t = 0; t < TT; t++) {
            float ev0[8], ev1[8];
            float p0 = 0.f, p1 = 0.f;
#pragma unroll
            for (int q = 0; q < 8; q++) {
                ev0[q] = e0[t * HH + lane + 32 * q];
                p0 = fmaf(ev0[q], h0[lane + 32 * q], p0);
            }
#pragma unroll
            for (int q = 0; q < 8; q++) {
                ev1[q] = e1[t * HH + lane + 32 * q];
                p1 = fmaf(ev1[q], h1[lane + 32 * q], p1);
            }
#pragma unroll
            for (int off = 16; off; off >>= 1) {
                p0 += __shfl_xor_sync(0xffffffffu, p0, off);
                p1 += __shfl_xor_sync(0xffffffffu, p1, off);
            }
            p0 *= mk0[t];
            p1 *= mk1[t];
            float nM0 = fmaxf(M0, p0);
            float c0f = __expf(M0 - nM0), w0f = __expf(p0 - nM0);
            S0 = S0 * c0f + w0f; M0 = nM0;
#pragma unroll
            for (int q = 0; q < 8; q++) cv0[q] = fmaf(w0f, ev0[q], cv0[q] * c0f);
            float nM1 = fmaxf(M1, p1);
            float c1f = __expf(M1 - nM1), w1f = __expf(p1 - nM1);
            S1 = S1 * c1f + w1f; M1 = nM1;
#pragma unroll
            for (int q = 0; q < 8; q++) cv1[q] = fmaf(w1f, ev1[q], cv1[q] * c1f);
        }
        float i0 = 1.f / S0, i1 = 1.f / S1;
#pragma unroll
        for (int q = 0; q < 8; q++) {
            cat[w * 512 +       lane + 32 * q] = cv0[q] * i0;
            cat[w * 512 + 256 + lane + 32 * q] = cv1[q] * i1;
        }
    }
    __syncthreads();
    // high slots (b2>=128): cat = concat of hsrc pairs == straight copy
    for (int i = tid; i < 4096; i += 256) cat[4096 + i] = hsrc[i];
    __syncthreads();

    // h_att = tanh(cat @ Watt^T + b_att): 16x256, K=512. thread owns column tid.
    {
        const float* wa = g_Watt + v * (512 * HH) + tid;
        float a[16];
#pragma unroll
        for (int j = 0; j < 16; j++) a[j] = 0.f;
        for (int k = 0; k < 512; k += 4) {
            float w0 = wa[(k + 0) * HH];
            float w1 = wa[(k + 1) * HH];
            float w2 = wa[(k + 2) * HH];
            float w3 = wa[(k + 3) * HH];
#pragma unroll
            for (int j = 0; j < 16; j++) {
                float4 c4 = *(const float4*)(cat + j * 512 + k);
                a[j] = fmaf(c4.x, w0, a[j]);
                a[j] = fmaf(c4.y, w1, a[j]);
                a[j] = fmaf(c4.z, w2, a[j]);
                a[j] = fmaf(c4.w, w3, a[j]);
            }
        }
        float bb = batt[v * HH + tid];
#pragma unroll
        for (int j = 0; j < 16; j++) hatt[j * 256 + tid] = tanhf(a[j] + bb);
    }
    if (tid < 128) ps_s[tid] = fmaf(prev_s[tid], scl_s[tid], mn_s[tid]);
    __syncthreads();

    // LSTM gates (overwrites A region — all cat/hsrc reads done)
    gates_gemm(ps_s, hatt, g_Wih + v * (FF * G4), g_Whh + v * (HH * G4), gates_s, tid);
    __syncthreads();

    // elementwise LSTM update; write h2 into hatt (consumed), persist states
#pragma unroll
    for (int j = 0; j < 16; j++) {
        const int hc = tid;
        float gi = gates_s[j * G4 +       hc] + bg[hc];
        float gf = gates_s[j * G4 + 256 + hc] + bg[256 + hc];
        float gg = gates_s[j * G4 + 512 + hc] + bg[512 + hc];
        float go = gates_s[j * G4 + 768 + hc] + bg[768 + hc];
        float c = sigf(gf) * c_s[j * 256 + hc] + sigf(gi) * tanhf(gg);
        float h = sigf(go) * tanhf(c);
        int b2 = ci + 16 * j;
        c_s[j * 256 + hc] = c;
        hatt[j * 256 + hc] = h;
        g_c[(b2 * VV + v) * HH + hc] = c;
        h_out[(b2 * VV + v) * HH + hc] = h;
    }
    __syncthreads();

    // output projection: out = relu(h2 @ Wout^T + b_out); store prev; emit clipped [:4]
    if (tid < 128) {
        int j = tid >> 3, f = tid & 7;
        int b2 = ci + 16 * j;
        float acc = bout[f];
        const float* wr = wout + f * HH;
        const float* hr = hatt + j * 256;
        for (int hh = 0; hh < 256; hh += 4) {
            float4 w4 = *(const float4*)(wr + hh);
            float4 h4 = *(const float4*)(hr + hh);
            acc = fmaf(w4.x, h4.x, acc);
            acc = fmaf(w4.y, h4.y, acc);
            acc = fmaf(w4.z, h4.z, acc);
            acc = fmaf(w4.w, h4.w, acc);
        }
        float o = fmaxf(acc, 0.f);
        g_prev[(b2 * VV + v) * FF + f] = o;
        if (f < OUTD)
            dout[((b2 * VV + v) * PP + p) * OUTD + f] = fminf(o, 1.f);
    }
}

// ---------------- launch ----------------
extern "C" void kernel_launch(void* const* d_in, const int* in_sizes, int n_in,
                              void* d_out, int out_size) {
    const float* seq  = (const float*)d_in[0];
    const float* mask = (const float*)d_in[4];
    const float* maxv = (const float*)d_in[5];
    const float* minv = (const float*)d_in[6];
    const float* Wih  = (const float*)d_in[7];
    const float* Whh  = (const float*)d_in[8];
    const float* bih  = (const float*)d_in[9];
    const float* bhh  = (const float*)d_in[10];
    const float* Watt = (const float*)d_in[11];
    const float* batt = (const float*)d_in[12];
    const float* Wout = (const float*)d_in[13];
    const float* bout = (const float*)d_in[14];
    float* out = (float*)d_out;

    cudaFuncSetAttribute(encoder_kernel, cudaFuncAttributeMaxDynamicSharedMemorySize, ENC_SMEM);
    cudaFuncSetAttribute(decoder_kernel, cudaFuncAttributeMaxDynamicSharedMemorySize, DEC_SMEM);

    prep_kernel<<<4096, 256>>>(Wih, Whh, bih, bhh, Watt);
    encoder_kernel<<<VV * 16, 256, ENC_SMEM>>>(seq);
    for (int p = 0; p < PP; p++) {
        decoder_kernel<<<VV * 16, 256, DEC_SMEM>>>(mask, maxv, minv, batt, Wout, bout, out, p);
    }
}